// round 3
// baseline (speedup 1.0000x reference)
#include <cuda_runtime.h>

#define POOL 7
#define NUM_ROIS 300
#define IMG_H 200
#define IMG_W 200
#define IMG_C 512

// One block per (roi, py, px) output position. 64 threads; each thread owns
// 8 channels (2x float4) -> 8 independent loads in flight per thread (MLP=8)
// at full grid parallelism (14700 blocks).
__global__ __launch_bounds__(64) void roi_pool_kernel(
    const float* __restrict__ img,   // [H, W, C]
    const float* __restrict__ rois,  // [NUM_ROIS, 4] (x, y, w, h) as float
    float* __restrict__ out)         // [NUM_ROIS, POOL, POOL, C]
{
    const int b   = blockIdx.x;              // 0 .. 14699
    const int roi = b / (POOL * POOL);
    const int pos = b - roi * (POOL * POOL);
    const int py  = pos / POOL;
    const int px  = pos - py * POOL;
    const int c   = threadIdx.x * 8;         // channels c .. c+7

    // ---- ROI geometry (uniform across block) ----
    const int rx = (int)__ldg(&rois[roi * 4 + 0]);
    const int ry = (int)__ldg(&rois[roi * 4 + 1]);
    const int rw = (int)__ldg(&rois[roi * 4 + 2]);
    const int rh = (int)__ldg(&rois[roi * 4 + 3]);

    const int x0 = min(max(rx, 0), IMG_W - 1);
    const int y0 = min(max(ry, 0), IMG_H - 1);
    const int w  = min(max(rw, 1), IMG_W - x0);
    const int h  = min(max(rh, 1), IMG_H - y0);

    // TF1 resize (align_corners=False): src = dst * (in/out); exact fp32 div
    const float sx = (float)w / (float)POOL;
    const float sy = (float)h / (float)POOL;
    const float xs = (float)px * sx;
    const float ys = (float)py * sy;

    int ix0 = (int)floorf(xs);
    int iy0 = (int)floorf(ys);
    const float fx = xs - (float)ix0;   // frac BEFORE clamp (matches reference)
    const float fy = ys - (float)iy0;
    ix0 = min(ix0, w - 1);
    iy0 = min(iy0, h - 1);
    const int ix1 = min(ix0 + 1, w - 1);
    const int iy1 = min(iy0 + 1, h - 1);

    const long p00 = ((long)(y0 + iy0) * IMG_W + (x0 + ix0)) * IMG_C + c;
    const long p01 = ((long)(y0 + iy0) * IMG_W + (x0 + ix1)) * IMG_C + c;
    const long p10 = ((long)(y0 + iy1) * IMG_W + (x0 + ix0)) * IMG_C + c;
    const long p11 = ((long)(y0 + iy1) * IMG_W + (x0 + ix1)) * IMG_C + c;

    // 8 independent 16B loads
    const float4 a00 = *(const float4*)(img + p00);
    const float4 b00 = *(const float4*)(img + p00 + 4);
    const float4 a01 = *(const float4*)(img + p01);
    const float4 b01 = *(const float4*)(img + p01 + 4);
    const float4 a10 = *(const float4*)(img + p10);
    const float4 b10 = *(const float4*)(img + p10 + 4);
    const float4 a11 = *(const float4*)(img + p11);
    const float4 b11 = *(const float4*)(img + p11 + 4);

    const float gx = 1.0f - fx;
    const float gy = 1.0f - fy;

    float4 r0, r1;
    r0.x = (a00.x * gx + a01.x * fx) * gy + (a10.x * gx + a11.x * fx) * fy;
    r0.y = (a00.y * gx + a01.y * fx) * gy + (a10.y * gx + a11.y * fx) * fy;
    r0.z = (a00.z * gx + a01.z * fx) * gy + (a10.z * gx + a11.z * fx) * fy;
    r0.w = (a00.w * gx + a01.w * fx) * gy + (a10.w * gx + a11.w * fx) * fy;
    r1.x = (b00.x * gx + b01.x * fx) * gy + (b10.x * gx + b11.x * fx) * fy;
    r1.y = (b00.y * gx + b01.y * fx) * gy + (b10.y * gx + b11.y * fx) * fy;
    r1.z = (b00.z * gx + b01.z * fx) * gy + (b10.z * gx + b11.z * fx) * fy;
    r1.w = (b00.w * gx + b01.w * fx) * gy + (b10.w * gx + b11.w * fx) * fy;

    float* o = out + (long)b * IMG_C + c;
    *(float4*)(o)     = r0;
    *(float4*)(o + 4) = r1;
}

extern "C" void kernel_launch(void* const* d_in, const int* in_sizes, int n_in,
                              void* d_out, int out_size)
{
    const float* img  = (const float*)d_in[0];
    const float* rois = (const float*)d_in[1];
    float* out = (float*)d_out;

    const int nblocks = NUM_ROIS * POOL * POOL;  // 14700
    roi_pool_kernel<<<nblocks, 64>>>(img, rois, out);
}

// round 4
// speedup vs baseline: 1.3133x; 1.3133x over previous
#include <cuda_runtime.h>

#define POOL 7
#define NUM_ROIS 300
#define IMG_H 200
#define IMG_W 200
#define IMG_C 512

// Horizontal coords for one px (matches reference semantics exactly)
__device__ __forceinline__ void hcoord(int px, float sx, int w, int x0,
                                       int& e0, int& e1, float& fx)
{
    const float xs = (float)px * sx;
    int ix0 = (int)floorf(xs);
    fx = xs - (float)ix0;          // frac BEFORE clamp
    ix0 = min(ix0, w - 1);
    const int ix1 = min(ix0 + 1, w - 1);
    e0 = (x0 + ix0) * IMG_C;
    e1 = (x0 + ix1) * IMG_C;
}

__device__ __forceinline__ float4 bilerp(float4 v00, float4 v01,
                                         float4 v10, float4 v11,
                                         float fx, float fy)
{
    const float gx = 1.0f - fx;
    const float gy = 1.0f - fy;
    float4 r;
    r.x = (v00.x * gx + v01.x * fx) * gy + (v10.x * gx + v11.x * fx) * fy;
    r.y = (v00.y * gx + v01.y * fx) * gy + (v10.y * gx + v11.y * fx) * fy;
    r.z = (v00.z * gx + v01.z * fx) * gy + (v10.z * gx + v11.z * fx) * fy;
    r.w = (v00.w * gx + v01.w * fx) * gy + (v10.w * gx + v11.w * fx) * fy;
    return r;
}

// One block per (roi, py, px-half). 128 threads, 4 channels each (float4).
// half 0 -> px {0,1,2,3}, half 1 -> px {4,5,6}.
// px positions processed in PAIRS with all 8 loads issued before any compute,
// giving true register-backed MLP=8.
__global__ __launch_bounds__(128) void roi_pool_kernel(
    const float* __restrict__ img,   // [H, W, C]
    const float* __restrict__ rois,  // [NUM_ROIS, 4]
    float* __restrict__ out)         // [NUM_ROIS, POOL, POOL, C]
{
    const int b    = blockIdx.x;          // 0..4199
    const int half = b & 1;
    const int rp   = b >> 1;              // roi*7 + py
    const int roi  = rp / POOL;
    const int py   = rp - roi * POOL;
    const int c    = threadIdx.x * 4;

    // ---- ROI geometry (uniform across block) ----
    const int rx = (int)__ldg(&rois[roi * 4 + 0]);
    const int ry = (int)__ldg(&rois[roi * 4 + 1]);
    const int rw = (int)__ldg(&rois[roi * 4 + 2]);
    const int rh = (int)__ldg(&rois[roi * 4 + 3]);

    const int x0 = min(max(rx, 0), IMG_W - 1);
    const int y0 = min(max(ry, 0), IMG_H - 1);
    const int w  = min(max(rw, 1), IMG_W - x0);
    const int h  = min(max(rh, 1), IMG_H - y0);

    const float sx = (float)w / (float)POOL;
    const float sy = (float)h / (float)POOL;

    // ---- vertical coords (fixed for this block) ----
    const float ys = (float)py * sy;
    int iy0 = (int)floorf(ys);
    const float fy = ys - (float)iy0;
    iy0 = min(iy0, h - 1);
    const int iy1 = min(iy0 + 1, h - 1);

    const float* __restrict__ row0 = img + ((y0 + iy0) * IMG_W) * IMG_C + c;
    const float* __restrict__ row1 = img + ((y0 + iy1) * IMG_W) * IMG_C + c;
    float* __restrict__ obase = out + (long)rp * (POOL * IMG_C) + c;

    const int px0 = half ? 4 : 0;

    // ================= pair 1: px0, px0+1 (always valid) =================
    {
        int e0a, e1a, e0b, e1b;
        float fxa, fxb;
        hcoord(px0,     sx, w, x0, e0a, e1a, fxa);
        hcoord(px0 + 1, sx, w, x0, e0b, e1b, fxb);

        // 8 independent loads, all issued before any compute
        const float4 A00 = *(const float4*)(row0 + e0a);
        const float4 A01 = *(const float4*)(row0 + e1a);
        const float4 A10 = *(const float4*)(row1 + e0a);
        const float4 A11 = *(const float4*)(row1 + e1a);
        const float4 B00 = *(const float4*)(row0 + e0b);
        const float4 B01 = *(const float4*)(row0 + e1b);
        const float4 B10 = *(const float4*)(row1 + e0b);
        const float4 B11 = *(const float4*)(row1 + e1b);

        const float4 ra = bilerp(A00, A01, A10, A11, fxa, fy);
        const float4 rb = bilerp(B00, B01, B10, B11, fxb, fy);
        __stcs((float4*)(obase + (px0)     * IMG_C), ra);
        __stcs((float4*)(obase + (px0 + 1) * IMG_C), rb);
    }

    // ================= pair 2: px0+2 (+ px0+3 only for half 0) ============
    if (half == 0) {
        int e0a, e1a, e0b, e1b;
        float fxa, fxb;
        hcoord(px0 + 2, sx, w, x0, e0a, e1a, fxa);
        hcoord(px0 + 3, sx, w, x0, e0b, e1b, fxb);

        const float4 A00 = *(const float4*)(row0 + e0a);
        const float4 A01 = *(const float4*)(row0 + e1a);
        const float4 A10 = *(const float4*)(row1 + e0a);
        const float4 A11 = *(const float4*)(row1 + e1a);
        const float4 B00 = *(const float4*)(row0 + e0b);
        const float4 B01 = *(const float4*)(row0 + e1b);
        const float4 B10 = *(const float4*)(row1 + e0b);
        const float4 B11 = *(const float4*)(row1 + e1b);

        const float4 ra = bilerp(A00, A01, A10, A11, fxa, fy);
        const float4 rb = bilerp(B00, B01, B10, B11, fxb, fy);
        __stcs((float4*)(obase + (px0 + 2) * IMG_C), ra);
        __stcs((float4*)(obase + (px0 + 3) * IMG_C), rb);
    } else {
        int e0a, e1a;
        float fxa;
        hcoord(px0 + 2, sx, w, x0, e0a, e1a, fxa);

        const float4 A00 = *(const float4*)(row0 + e0a);
        const float4 A01 = *(const float4*)(row0 + e1a);
        const float4 A10 = *(const float4*)(row1 + e0a);
        const float4 A11 = *(const float4*)(row1 + e1a);

        const float4 ra = bilerp(A00, A01, A10, A11, fxa, fy);
        __stcs((float4*)(obase + (px0 + 2) * IMG_C), ra);
    }
}

extern "C" void kernel_launch(void* const* d_in, const int* in_sizes, int n_in,
                              void* d_out, int out_size)
{
    const float* img  = (const float*)d_in[0];
    const float* rois = (const float*)d_in[1];
    float* out = (float*)d_out;

    const int nblocks = NUM_ROIS * POOL * 2;  // 4200
    roi_pool_kernel<<<nblocks, 128>>>(img, rois, out);
}